// round 1
// baseline (speedup 1.0000x reference)
#include <cuda_runtime.h>
#include <cuda_bf16.h>
#include <math.h>

#define MAX_N 50000
#define CH    96   // max hidden channels
#define BN_EPS 1e-5f

// -------- scratch (device globals; no allocation allowed) --------
__device__ float d_t  [MAX_N * CH];   // GEMM output (pre-aggregation)
__device__ float d_agg[MAX_N * CH];   // aggregation buffer
__device__ float d_h  [MAX_N * CH];   // layer activation
__device__ float d_stats[2 * CH];     // per-channel sum / sumsq
__device__ float d_scale[CH];
__device__ float d_shift[CH];

// -------- zero kernel --------
__global__ void zero_kernel(float* __restrict__ p, long n) {
    long i = (long)blockIdx.x * blockDim.x + threadIdx.x;
    long stride = (long)gridDim.x * blockDim.x;
    for (; i < n; i += stride) p[i] = 0.0f;
}

// -------- dense GEMM: C[nrows, COUT] = A[nrows, CIN] @ W[CIN, COUT] --------
// blockDim = (COUT/4, ROWS_PER_BLOCK). W cached in dynamic smem.
template<int CIN, int COUT>
__global__ void gemm_kernel(const float* __restrict__ A,
                            const float* __restrict__ W,
                            float* __restrict__ C, int nrows) {
    extern __shared__ float Ws[];
    int tid = threadIdx.y * blockDim.x + threadIdx.x;
    int nthreads = blockDim.x * blockDim.y;
    for (int i = tid; i < CIN * COUT; i += nthreads) Ws[i] = W[i];
    __syncthreads();

    int row = blockIdx.x * blockDim.y + threadIdx.y;
    if (row >= nrows) return;
    int c0 = threadIdx.x * 4;

    float acc0 = 0.f, acc1 = 0.f, acc2 = 0.f, acc3 = 0.f;
    const float* a = A + (long)row * CIN;
#pragma unroll 8
    for (int k = 0; k < CIN; k++) {
        float av = a[k];
        const float* w = Ws + k * COUT + c0;
        acc0 = fmaf(av, w[0], acc0);
        acc1 = fmaf(av, w[1], acc1);
        acc2 = fmaf(av, w[2], acc2);
        acc3 = fmaf(av, w[3], acc3);
    }
    float4* out = (float4*)(C + (long)row * COUT + c0);
    *out = make_float4(acc0, acc1, acc2, acc3);
}

// -------- edge scatter-aggregate: agg[row] += ew * src[col] --------
// one thread per (edge, float4-group); vectorized RED (sm_90+).
template<int C>
__global__ void scatter_kernel(const float* __restrict__ src,
                               const float* __restrict__ ew,
                               const int* __restrict__ row,
                               const int* __restrict__ col,
                               float* __restrict__ agg, int nedges) {
    const int G = C / 4;
    long idx = (long)blockIdx.x * blockDim.x + threadIdx.x;
    if (idx >= (long)nedges * G) return;
    int e = (int)(idx / G);
    int g = (int)(idx % G);
    float w = __ldg(ew + e);
    int c = __ldg(col + e);
    int r = __ldg(row + e);
    float4 v = *(const float4*)(src + (long)c * C + g * 4);
    float* dst = agg + (long)r * C + g * 4;
    asm volatile("red.global.add.v4.f32 [%0], {%1, %2, %3, %4};"
                 :: "l"(dst), "f"(v.x * w), "f"(v.y * w), "f"(v.z * w), "f"(v.w * w)
                 : "memory");
}

// -------- BN stats: per-channel sum and sumsq --------
template<int C>
__global__ void stats_kernel(const float* __restrict__ h,
                             float* __restrict__ stats, int nrows) {
    __shared__ float ssum[C];
    __shared__ float ssq[C];
    for (int i = threadIdx.x; i < C; i += blockDim.x) { ssum[i] = 0.f; ssq[i] = 0.f; }
    __syncthreads();
    long total = (long)nrows * C;
    long stride = (long)gridDim.x * blockDim.x;
    for (long idx = (long)blockIdx.x * blockDim.x + threadIdx.x; idx < total; idx += stride) {
        float v = h[idx];
        int c = (int)(idx % C);
        atomicAdd(&ssum[c], v);
        atomicAdd(&ssq[c], v * v);
    }
    __syncthreads();
    for (int i = threadIdx.x; i < C; i += blockDim.x) {
        atomicAdd(&stats[i], ssum[i]);
        atomicAdd(&stats[C + i], ssq[i]);
    }
}

// -------- BN finalize: scale/shift per channel --------
template<int C>
__global__ void bn_finalize_kernel(const float* __restrict__ stats,
                                   const float* __restrict__ gamma,
                                   const float* __restrict__ beta,
                                   float* __restrict__ scale,
                                   float* __restrict__ shift, int nrows) {
    int c = threadIdx.x;
    if (c >= C) return;
    float n = (float)nrows;
    float mean = stats[c] / n;
    float var = stats[C + c] / n - mean * mean;
    float inv = rsqrtf(var + BN_EPS);
    float sc = gamma[c] * inv;
    scale[c] = sc;
    shift[c] = beta[c] - mean * sc;
}

// -------- normalize + relu --------
template<int C>
__global__ void normrelu_kernel(const float* __restrict__ agg,
                                const float* __restrict__ scale,
                                const float* __restrict__ shift,
                                float* __restrict__ out, int nrows) {
    long total = (long)nrows * C;
    long stride = (long)gridDim.x * blockDim.x;
    for (long idx = (long)blockIdx.x * blockDim.x + threadIdx.x; idx < total; idx += stride) {
        int c = (int)(idx % C);
        float v = fmaf(agg[idx], scale[c], shift[c]);
        out[idx] = fmaxf(v, 0.0f);
    }
}

// -------- log_softmax over 64 channels (one warp per row), + bias b3 --------
__global__ void lsm_kernel(const float* __restrict__ agg,
                           const float* __restrict__ b,
                           float* __restrict__ out, int nrows) {
    int gw = (blockIdx.x * blockDim.x + threadIdx.x) >> 5;
    int lane = threadIdx.x & 31;
    if (gw >= nrows) return;
    const float* a = agg + (long)gw * 64;
    float v0 = a[lane]      + b[lane];
    float v1 = a[lane + 32] + b[lane + 32];
    float m = fmaxf(v0, v1);
#pragma unroll
    for (int o = 16; o; o >>= 1) m = fmaxf(m, __shfl_xor_sync(0xFFFFFFFFu, m, o));
    float s = __expf(v0 - m) + __expf(v1 - m);
#pragma unroll
    for (int o = 16; o; o >>= 1) s += __shfl_xor_sync(0xFFFFFFFFu, s, o);
    float l = m + __logf(s);
    float* o_ = out + (long)gw * 64;
    o_[lane]      = v0 - l;
    o_[lane + 32] = v1 - l;
}

// ============================================================================
extern "C" void kernel_launch(void* const* d_in, const int* in_sizes, int n_in,
                              void* d_out, int out_size) {
    const float* x   = (const float*)d_in[0];
    const float* ew  = (const float*)d_in[1];
    const int*   row = (const int*)  d_in[2];
    const int*   col = (const int*)  d_in[3];
    const float* W1  = (const float*)d_in[4];
    // b1 = d_in[5]  -- absorbed by BatchNorm mean (exactly), skipped
    const float* W2  = (const float*)d_in[6];
    // b2 = d_in[7]  -- absorbed by BatchNorm mean (exactly), skipped
    const float* W3  = (const float*)d_in[8];
    const float* b3  = (const float*)d_in[9];
    const float* g1  = (const float*)d_in[10];
    const float* be1 = (const float*)d_in[11];
    const float* g2  = (const float*)d_in[12];
    const float* be2 = (const float*)d_in[13];

    int N = in_sizes[0] / 128;
    int E = in_sizes[1];
    float* out = (float*)d_out;

    float *t, *agg, *h, *stats, *scale, *shift;
    cudaGetSymbolAddress((void**)&t,     d_t);
    cudaGetSymbolAddress((void**)&agg,   d_agg);
    cudaGetSymbolAddress((void**)&h,     d_h);
    cudaGetSymbolAddress((void**)&stats, d_stats);
    cudaGetSymbolAddress((void**)&scale, d_scale);
    cudaGetSymbolAddress((void**)&shift, d_shift);

    const int ZB = 256;
    const int SB = 256;

    // ================= Layer 1: x[N,128] -> h[N,96] =================
    {
        long nz = (long)N * 96;
        zero_kernel<<<(int)((nz + ZB - 1) / ZB), ZB>>>(agg, nz);
        zero_kernel<<<1, 192>>>(stats, 192);
        gemm_kernel<128, 96><<<(N + 7) / 8, dim3(24, 8), 128 * 96 * sizeof(float)>>>(x, W1, t, N);
        long nw = (long)E * 24;
        scatter_kernel<96><<<(int)((nw + SB - 1) / SB), SB>>>(t, ew, row, col, agg, E);
        stats_kernel<96><<<1024, 256>>>(agg, stats, N);
        bn_finalize_kernel<96><<<1, 96>>>(stats, g1, be1, scale, shift, N);
        normrelu_kernel<96><<<2048, 256>>>(agg, scale, shift, h, N);
    }

    // ================= Layer 2: h[N,96] -> h[N,96] =================
    {
        long nz = (long)N * 96;
        zero_kernel<<<(int)((nz + ZB - 1) / ZB), ZB>>>(agg, nz);
        zero_kernel<<<1, 192>>>(stats, 192);
        gemm_kernel<96, 96><<<(N + 7) / 8, dim3(24, 8), 96 * 96 * sizeof(float)>>>(h, W2, t, N);
        long nw = (long)E * 24;
        scatter_kernel<96><<<(int)((nw + SB - 1) / SB), SB>>>(t, ew, row, col, agg, E);
        stats_kernel<96><<<1024, 256>>>(agg, stats, N);
        bn_finalize_kernel<96><<<1, 96>>>(stats, g2, be2, scale, shift, N);
        normrelu_kernel<96><<<2048, 256>>>(agg, scale, shift, h, N);
    }

    // ================= Layer 3: h[N,96] -> out[N,64] =================
    {
        long nz = (long)N * 64;
        zero_kernel<<<(int)((nz + ZB - 1) / ZB), ZB>>>(agg, nz);
        gemm_kernel<96, 64><<<(N + 7) / 8, dim3(16, 8), 96 * 64 * sizeof(float)>>>(h, W3, t, N);
        long nw = (long)E * 16;
        scatter_kernel<64><<<(int)((nw + SB - 1) / SB), SB>>>(t, ew, row, col, agg, E);
        lsm_kernel<<<(N * 32 + 255) / 256, 256>>>(agg, b3, out, N);
    }
}

// round 2
// speedup vs baseline: 1.6326x; 1.6326x over previous
#include <cuda_runtime.h>
#include <cuda_bf16.h>
#include <math.h>

#define MAX_N 50000
#define CH    96
#define BN_EPS 1e-5f

// -------- scratch (device globals; no allocation allowed) --------
__device__ float d_t  [MAX_N * CH];   // GEMM output (pre-aggregation)
__device__ float d_agg[MAX_N * CH];   // aggregation buffer
__device__ float d_stats[2 * CH];     // per-channel sum / sumsq
__device__ float d_scale[CH];
__device__ float d_shift[CH];

// ============================================================================
// Register-blocked GEMM with optional fused BatchNorm+ReLU on the INPUT:
//   C[nrows, COUT] = act(A) @ W,  act(a) = relu(a*scale[k] + shift[k]) if scale
// Tile: 32 rows x COUT per block. Each thread computes a 4x4 output tile.
// W cached in dynamic smem (once per 32 rows); A staged transposed in smem.
// ============================================================================
template<int CIN, int COUT>
__global__ void gemm_bn_kernel(const float* __restrict__ A,
                               const float* __restrict__ W,
                               const float* __restrict__ scale,
                               const float* __restrict__ shift,
                               float* __restrict__ C, int nrows) {
    constexpr int TM = 32;
    constexpr int TX = COUT / 4;      // thread cols (channel groups)
    constexpr int TY = TM / 4;        // 8 thread rows
    constexpr int NT = TX * TY;
    constexpr int APAD = TM + 4;      // 36-float row stride (16B-aligned groups)
    constexpr int KG = CIN / 4;

    extern __shared__ float smem[];
    float* Ws = smem;                 // [CIN * COUT]
    float* As = smem + CIN * COUT;    // [CIN][APAD]

    int tid = threadIdx.y * TX + threadIdx.x;

    // load W (coalesced float4)
    for (int i = tid; i < CIN * COUT / 4; i += NT)
        ((float4*)Ws)[i] = ((const float4*)W)[i];

    // stage A tile transposed, with optional BN+ReLU applied per input channel
    int row0 = blockIdx.x * TM;
    for (int i = tid; i < TM * KG; i += NT) {
        int r  = i / KG;
        int kg = i % KG;
        int grow = row0 + r;
        float4 v = make_float4(0.f, 0.f, 0.f, 0.f);
        if (grow < nrows) v = *(const float4*)(A + (long)grow * CIN + kg * 4);
        if (scale) {
            int k = kg * 4;
            v.x = fmaxf(fmaf(v.x, scale[k+0], shift[k+0]), 0.f);
            v.y = fmaxf(fmaf(v.y, scale[k+1], shift[k+1]), 0.f);
            v.z = fmaxf(fmaf(v.z, scale[k+2], shift[k+2]), 0.f);
            v.w = fmaxf(fmaf(v.w, scale[k+3], shift[k+3]), 0.f);
        }
        As[(kg*4+0) * APAD + r] = v.x;
        As[(kg*4+1) * APAD + r] = v.y;
        As[(kg*4+2) * APAD + r] = v.z;
        As[(kg*4+3) * APAD + r] = v.w;
    }
    __syncthreads();

    int c0 = threadIdx.x * 4;
    int r0 = threadIdx.y * 4;

    float acc00=0,acc01=0,acc02=0,acc03=0;
    float acc10=0,acc11=0,acc12=0,acc13=0;
    float acc20=0,acc21=0,acc22=0,acc23=0;
    float acc30=0,acc31=0,acc32=0,acc33=0;

#pragma unroll 4
    for (int k = 0; k < CIN; k++) {
        float4 w = *(const float4*)(Ws + k * COUT + c0);
        const float* ar = As + k * APAD + r0;
        float a0 = ar[0], a1 = ar[1], a2 = ar[2], a3 = ar[3];
        acc00 = fmaf(a0, w.x, acc00); acc01 = fmaf(a0, w.y, acc01);
        acc02 = fmaf(a0, w.z, acc02); acc03 = fmaf(a0, w.w, acc03);
        acc10 = fmaf(a1, w.x, acc10); acc11 = fmaf(a1, w.y, acc11);
        acc12 = fmaf(a1, w.z, acc12); acc13 = fmaf(a1, w.w, acc13);
        acc20 = fmaf(a2, w.x, acc20); acc21 = fmaf(a2, w.y, acc21);
        acc22 = fmaf(a2, w.z, acc22); acc23 = fmaf(a2, w.w, acc23);
        acc30 = fmaf(a3, w.x, acc30); acc31 = fmaf(a3, w.y, acc31);
        acc32 = fmaf(a3, w.z, acc32); acc33 = fmaf(a3, w.w, acc33);
    }

    long base = (long)(row0 + r0) * COUT + c0;
    if (row0 + r0 + 0 < nrows) *(float4*)(C + base + 0L*COUT) = make_float4(acc00,acc01,acc02,acc03);
    if (row0 + r0 + 1 < nrows) *(float4*)(C + base + 1L*COUT) = make_float4(acc10,acc11,acc12,acc13);
    if (row0 + r0 + 2 < nrows) *(float4*)(C + base + 2L*COUT) = make_float4(acc20,acc21,acc22,acc23);
    if (row0 + r0 + 3 < nrows) *(float4*)(C + base + 3L*COUT) = make_float4(acc30,acc31,acc32,acc33);
}

// -------- edge scatter-aggregate: agg[row] += ew * src[col] (RED.v4) --------
template<int C>
__global__ void scatter_kernel(const float* __restrict__ src,
                               const float* __restrict__ ew,
                               const int* __restrict__ row,
                               const int* __restrict__ col,
                               float* __restrict__ agg, int nedges) {
    const int G = C / 4;
    long idx = (long)blockIdx.x * blockDim.x + threadIdx.x;
    if (idx >= (long)nedges * G) return;
    int e = (int)(idx / G);
    int g = (int)(idx % G);
    float w = __ldg(ew + e);
    int c = __ldg(col + e);
    int r = __ldg(row + e);
    float4 v = *(const float4*)(src + (long)c * C + g * 4);
    float* dst = agg + (long)r * C + g * 4;
    asm volatile("red.global.add.v4.f32 [%0], {%1, %2, %3, %4};"
                 :: "l"(dst), "f"(v.x * w), "f"(v.y * w), "f"(v.z * w), "f"(v.w * w)
                 : "memory");
}

// -------- BN stats: register-accumulating, one thread per channel ----------
__global__ void stats96_kernel(const float* __restrict__ h,
                               float* __restrict__ stats, int nrows) {
    int c = threadIdx.x;   // blockDim.x == 96
    float s = 0.f, q = 0.f;
    for (int r = blockIdx.x; r < nrows; r += gridDim.x) {
        float v = h[(long)r * 96 + c];
        s += v;
        q = fmaf(v, v, q);
    }
    atomicAdd(&stats[c], s);
    atomicAdd(&stats[96 + c], q);
}

// -------- BN finalize: per-channel scale/shift --------
__global__ void bn_finalize_kernel(const float* __restrict__ stats,
                                   const float* __restrict__ gamma,
                                   const float* __restrict__ beta,
                                   float* __restrict__ scale,
                                   float* __restrict__ shift, int nrows) {
    int c = threadIdx.x;
    if (c >= 96) return;
    float n = (float)nrows;
    float mean = stats[c] / n;
    float var = stats[96 + c] / n - mean * mean;
    float inv = rsqrtf(var + BN_EPS);
    float sc = gamma[c] * inv;
    scale[c] = sc;
    shift[c] = beta[c] - mean * sc;
}

// -------- log_softmax over 64 channels (one warp per row), + bias b3 --------
__global__ void lsm_kernel(const float* __restrict__ agg,
                           const float* __restrict__ b,
                           float* __restrict__ out, int nrows) {
    int gw = (blockIdx.x * blockDim.x + threadIdx.x) >> 5;
    int lane = threadIdx.x & 31;
    if (gw >= nrows) return;
    const float* a = agg + (long)gw * 64;
    float v0 = a[lane]      + b[lane];
    float v1 = a[lane + 32] + b[lane + 32];
    float m = fmaxf(v0, v1);
#pragma unroll
    for (int o = 16; o; o >>= 1) m = fmaxf(m, __shfl_xor_sync(0xFFFFFFFFu, m, o));
    float s = __expf(v0 - m) + __expf(v1 - m);
#pragma unroll
    for (int o = 16; o; o >>= 1) s += __shfl_xor_sync(0xFFFFFFFFu, s, o);
    float l = m + __logf(s);
    float* o_ = out + (long)gw * 64;
    o_[lane]      = v0 - l;
    o_[lane + 32] = v1 - l;
}

// ============================================================================
extern "C" void kernel_launch(void* const* d_in, const int* in_sizes, int n_in,
                              void* d_out, int out_size) {
    const float* x   = (const float*)d_in[0];
    const float* ew  = (const float*)d_in[1];
    const int*   row = (const int*)  d_in[2];
    const int*   col = (const int*)  d_in[3];
    const float* W1  = (const float*)d_in[4];
    // b1 = d_in[5]  -- absorbed exactly by BatchNorm mean, skipped
    const float* W2  = (const float*)d_in[6];
    // b2 = d_in[7]  -- absorbed exactly by BatchNorm mean, skipped
    const float* W3  = (const float*)d_in[8];
    const float* b3  = (const float*)d_in[9];
    const float* g1  = (const float*)d_in[10];
    const float* be1 = (const float*)d_in[11];
    const float* g2  = (const float*)d_in[12];
    const float* be2 = (const float*)d_in[13];

    int N = in_sizes[0] / 128;
    int E = in_sizes[1];
    float* out = (float*)d_out;

    float *t, *agg, *stats, *scale, *shift;
    cudaGetSymbolAddress((void**)&t,     d_t);
    cudaGetSymbolAddress((void**)&agg,   d_agg);
    cudaGetSymbolAddress((void**)&stats, d_stats);
    cudaGetSymbolAddress((void**)&scale, d_scale);
    cudaGetSymbolAddress((void**)&shift, d_shift);

    // dynamic smem sizes (W + padded transposed A tile)
    const int SM1 = (128*96 + 128*36) * sizeof(float);  // 67584
    const int SM2 = (96*96  + 96*36)  * sizeof(float);  // 50688
    const int SM3 = (96*64  + 96*36)  * sizeof(float);  // 38400
    cudaFuncSetAttribute(gemm_bn_kernel<128,96>, cudaFuncAttributeMaxDynamicSharedMemorySize, SM1);
    cudaFuncSetAttribute(gemm_bn_kernel<96,96>,  cudaFuncAttributeMaxDynamicSharedMemorySize, SM2);
    cudaFuncSetAttribute(gemm_bn_kernel<96,64>,  cudaFuncAttributeMaxDynamicSharedMemorySize, SM3);

    const int SB = 256;
    int gblocks = (N + 31) / 32;

    // ================= Layer 1: x[N,128] -> agg1[N,96] =================
    cudaMemsetAsync(agg, 0, (long)N * 96 * sizeof(float));
    cudaMemsetAsync(stats, 0, 192 * sizeof(float));
    gemm_bn_kernel<128,96><<<gblocks, dim3(24,8), SM1>>>(x, W1, nullptr, nullptr, t, N);
    {
        long nw = (long)E * 24;
        scatter_kernel<96><<<(int)((nw + SB - 1) / SB), SB>>>(t, ew, row, col, agg, E);
    }
    stats96_kernel<<<1024, 96>>>(agg, stats, N);
    bn_finalize_kernel<<<1, 96>>>(stats, g1, be1, scale, shift, N);

    // ================= Layer 2: relu(bn(agg1)) -> agg2[N,96] =================
    // BN+ReLU fused into the GEMM's A-staging
    gemm_bn_kernel<96,96><<<gblocks, dim3(24,8), SM2>>>(agg, W2, scale, shift, t, N);
    cudaMemsetAsync(agg, 0, (long)N * 96 * sizeof(float));
    cudaMemsetAsync(stats, 0, 192 * sizeof(float));
    {
        long nw = (long)E * 24;
        scatter_kernel<96><<<(int)((nw + SB - 1) / SB), SB>>>(t, ew, row, col, agg, E);
    }
    stats96_kernel<<<1024, 96>>>(agg, stats, N);
    bn_finalize_kernel<<<1, 96>>>(stats, g2, be2, scale, shift, N);

    // ================= Layer 3: relu(bn(agg2)) -> out[N,64] =================
    gemm_bn_kernel<96,64><<<gblocks, dim3(16,8), SM3>>>(agg, W3, scale, shift, t, N);
    cudaMemsetAsync(agg, 0, (long)N * 64 * sizeof(float));
    {
        long nw = (long)E * 16;
        scatter_kernel<64><<<(int)((nw + SB - 1) / SB), SB>>>(t, ew, row, col, agg, E);
    }
    lsm_kernel<<<(N * 32 + 255) / 256, 256>>>(agg, b3, out, N);
}

// round 3
// speedup vs baseline: 1.6601x; 1.0169x over previous
#include <cuda_runtime.h>
#include <cuda_bf16.h>
#include <math.h>

#define MAX_N 50000
#define MAX_E 800000
#define CH    96
#define BN_EPS 1e-5f

// -------- scratch (device globals; no allocation allowed) --------
__device__ float d_t   [MAX_N * CH];     // GEMM output (pre-aggregation)
__device__ float d_agg [MAX_N * CH];     // aggregation output
__device__ float d_stats[2 * CH];        // per-channel sum / sumsq
__device__ float d_scale[CH];
__device__ float d_shift[CH];
// CSR build scratch
__device__ int   d_deg   [MAX_N];
__device__ int   d_starts[MAX_N + 1];
__device__ int   d_cursor[MAX_N];
__device__ int   d_ecol  [MAX_E];
__device__ float d_eew   [MAX_E];

// ============================================================================
// CSR build: histogram -> scan -> permute (runs every call; deterministic work)
// ============================================================================
__global__ void hist_kernel(const int* __restrict__ row, int* __restrict__ deg, int E) {
    int i = blockIdx.x * blockDim.x + threadIdx.x;
    if (i < E) atomicAdd(&deg[row[i]], 1);
}

__global__ void scan_kernel(const int* __restrict__ deg,
                            int* __restrict__ starts,
                            int* __restrict__ cursor, int N) {
    __shared__ int part[1024];
    int t = threadIdx.x;
    int chunk = (N + 1023) / 1024;
    int lo = t * chunk;
    int hi = lo + chunk; if (hi > N) hi = N; if (lo > N) lo = N;
    int s = 0;
    for (int i = lo; i < hi; i++) s += deg[i];
    part[t] = s;
    __syncthreads();
    // Hillis-Steele inclusive scan
    for (int o = 1; o < 1024; o <<= 1) {
        int v = (t >= o) ? part[t - o] : 0;
        __syncthreads();
        part[t] += v;
        __syncthreads();
    }
    int base = (t == 0) ? 0 : part[t - 1];
    for (int i = lo; i < hi; i++) {
        starts[i] = base;
        cursor[i] = base;
        base += deg[i];
    }
    if (t == 1023) starts[N] = part[1023];
}

__global__ void permute_kernel(const int* __restrict__ row,
                               const int* __restrict__ col,
                               const float* __restrict__ ew,
                               int* __restrict__ cursor,
                               int* __restrict__ ecol,
                               float* __restrict__ eew, int E) {
    int i = blockIdx.x * blockDim.x + threadIdx.x;
    if (i >= E) return;
    int p = atomicAdd(&cursor[row[i]], 1);
    ecol[p] = col[i];
    eew[p]  = ew[i];
}

// ============================================================================
// Register-blocked GEMM with optional fused BatchNorm+ReLU on the INPUT.
// Tile: 32 rows x COUT per block; each thread computes a 4x4 output tile.
// ============================================================================
template<int CIN, int COUT>
__global__ void gemm_bn_kernel(const float* __restrict__ A,
                               const float* __restrict__ W,
                               const float* __restrict__ scale,
                               const float* __restrict__ shift,
                               float* __restrict__ C, int nrows) {
    constexpr int TM = 32;
    constexpr int TX = COUT / 4;
    constexpr int TY = TM / 4;
    constexpr int NT = TX * TY;
    constexpr int APAD = TM + 4;
    constexpr int KG = CIN / 4;

    extern __shared__ float smem[];
    float* Ws = smem;
    float* As = smem + CIN * COUT;

    int tid = threadIdx.y * TX + threadIdx.x;
    for (int i = tid; i < CIN * COUT / 4; i += NT)
        ((float4*)Ws)[i] = ((const float4*)W)[i];

    int row0 = blockIdx.x * TM;
    for (int i = tid; i < TM * KG; i += NT) {
        int r  = i / KG;
        int kg = i % KG;
        int grow = row0 + r;
        float4 v = make_float4(0.f, 0.f, 0.f, 0.f);
        if (grow < nrows) v = *(const float4*)(A + (long)grow * CIN + kg * 4);
        if (scale) {
            int k = kg * 4;
            v.x = fmaxf(fmaf(v.x, scale[k+0], shift[k+0]), 0.f);
            v.y = fmaxf(fmaf(v.y, scale[k+1], shift[k+1]), 0.f);
            v.z = fmaxf(fmaf(v.z, scale[k+2], shift[k+2]), 0.f);
            v.w = fmaxf(fmaf(v.w, scale[k+3], shift[k+3]), 0.f);
        }
        As[(kg*4+0) * APAD + r] = v.x;
        As[(kg*4+1) * APAD + r] = v.y;
        As[(kg*4+2) * APAD + r] = v.z;
        As[(kg*4+3) * APAD + r] = v.w;
    }
    __syncthreads();

    int c0 = threadIdx.x * 4;
    int r0 = threadIdx.y * 4;

    float acc00=0,acc01=0,acc02=0,acc03=0;
    float acc10=0,acc11=0,acc12=0,acc13=0;
    float acc20=0,acc21=0,acc22=0,acc23=0;
    float acc30=0,acc31=0,acc32=0,acc33=0;

#pragma unroll 4
    for (int k = 0; k < CIN; k++) {
        float4 w = *(const float4*)(Ws + k * COUT + c0);
        const float* ar = As + k * APAD + r0;
        float a0 = ar[0], a1 = ar[1], a2 = ar[2], a3 = ar[3];
        acc00 = fmaf(a0, w.x, acc00); acc01 = fmaf(a0, w.y, acc01);
        acc02 = fmaf(a0, w.z, acc02); acc03 = fmaf(a0, w.w, acc03);
        acc10 = fmaf(a1, w.x, acc10); acc11 = fmaf(a1, w.y, acc11);
        acc12 = fmaf(a1, w.z, acc12); acc13 = fmaf(a1, w.w, acc13);
        acc20 = fmaf(a2, w.x, acc20); acc21 = fmaf(a2, w.y, acc21);
        acc22 = fmaf(a2, w.z, acc22); acc23 = fmaf(a2, w.w, acc23);
        acc30 = fmaf(a3, w.x, acc30); acc31 = fmaf(a3, w.y, acc31);
        acc32 = fmaf(a3, w.z, acc32); acc33 = fmaf(a3, w.w, acc33);
    }

    long base = (long)(row0 + r0) * COUT + c0;
    if (row0 + r0 + 0 < nrows) *(float4*)(C + base + 0L*COUT) = make_float4(acc00,acc01,acc02,acc03);
    if (row0 + r0 + 1 < nrows) *(float4*)(C + base + 1L*COUT) = make_float4(acc10,acc11,acc12,acc13);
    if (row0 + r0 + 2 < nrows) *(float4*)(C + base + 2L*COUT) = make_float4(acc20,acc21,acc22,acc23);
    if (row0 + r0 + 3 < nrows) *(float4*)(C + base + 3L*COUT) = make_float4(acc30,acc31,acc32,acc33);
}

// ============================================================================
// CSR gather-aggregate (no atomics): one warp per node, 96 channels.
// lane owns channels {lane, lane+32, lane+64}. Coalesced 384B row reads.
// ============================================================================
__global__ void gather96_kernel(const int* __restrict__ starts,
                                const int* __restrict__ ecol,
                                const float* __restrict__ eew,
                                const float* __restrict__ src,
                                float* __restrict__ dst, int N) {
    int w = (blockIdx.x * blockDim.x + threadIdx.x) >> 5;
    int lane = threadIdx.x & 31;
    if (w >= N) return;
    int s = __ldg(starts + w), e = __ldg(starts + w + 1);
    float a0 = 0.f, a1 = 0.f, a2 = 0.f;
    int c = 0; float wt = 0.f;
    if (s < e) { c = __ldg(ecol + s); wt = __ldg(eew + s); }
    for (int i = s; i < e; i++) {
        int cc = c; float cw = wt;
        if (i + 1 < e) { c = __ldg(ecol + i + 1); wt = __ldg(eew + i + 1); }
        const float* p = src + (long)cc * 96;
        a0 = fmaf(cw, __ldg(p + lane),      a0);
        a1 = fmaf(cw, __ldg(p + lane + 32), a1);
        a2 = fmaf(cw, __ldg(p + lane + 64), a2);
    }
    float* d = dst + (long)w * 96;
    d[lane]      = a0;
    d[lane + 32] = a1;
    d[lane + 64] = a2;
}

// ============================================================================
// CSR gather (64 ch) fused with +bias and log_softmax -> final output.
// ============================================================================
__global__ void gather64_lsm_kernel(const int* __restrict__ starts,
                                    const int* __restrict__ ecol,
                                    const float* __restrict__ eew,
                                    const float* __restrict__ src,
                                    const float* __restrict__ b,
                                    float* __restrict__ out, int N) {
    int w = (blockIdx.x * blockDim.x + threadIdx.x) >> 5;
    int lane = threadIdx.x & 31;
    if (w >= N) return;
    int s = __ldg(starts + w), e = __ldg(starts + w + 1);
    float a0 = 0.f, a1 = 0.f;
    int c = 0; float wt = 0.f;
    if (s < e) { c = __ldg(ecol + s); wt = __ldg(eew + s); }
    for (int i = s; i < e; i++) {
        int cc = c; float cw = wt;
        if (i + 1 < e) { c = __ldg(ecol + i + 1); wt = __ldg(eew + i + 1); }
        const float* p = src + (long)cc * 64;
        a0 = fmaf(cw, __ldg(p + lane),      a0);
        a1 = fmaf(cw, __ldg(p + lane + 32), a1);
    }
    float v0 = a0 + __ldg(b + lane);
    float v1 = a1 + __ldg(b + lane + 32);
    float m = fmaxf(v0, v1);
#pragma unroll
    for (int o = 16; o; o >>= 1) m = fmaxf(m, __shfl_xor_sync(0xFFFFFFFFu, m, o));
    float sum = __expf(v0 - m) + __expf(v1 - m);
#pragma unroll
    for (int o = 16; o; o >>= 1) sum += __shfl_xor_sync(0xFFFFFFFFu, sum, o);
    float l = m + __logf(sum);
    float* o_ = out + (long)w * 64;
    o_[lane]      = v0 - l;
    o_[lane + 32] = v1 - l;
}

// -------- BN stats: register-accumulating, one thread per channel ----------
__global__ void stats96_kernel(const float* __restrict__ h,
                               float* __restrict__ stats, int nrows) {
    int c = threadIdx.x;   // blockDim.x == 96
    float s = 0.f, q = 0.f;
    for (int r = blockIdx.x; r < nrows; r += gridDim.x) {
        float v = h[(long)r * 96 + c];
        s += v;
        q = fmaf(v, v, q);
    }
    atomicAdd(&stats[c], s);
    atomicAdd(&stats[96 + c], q);
}

// -------- BN finalize: per-channel scale/shift --------
__global__ void bn_finalize_kernel(const float* __restrict__ stats,
                                   const float* __restrict__ gamma,
                                   const float* __restrict__ beta,
                                   float* __restrict__ scale,
                                   float* __restrict__ shift, int nrows) {
    int c = threadIdx.x;
    if (c >= 96) return;
    float n = (float)nrows;
    float mean = stats[c] / n;
    float var = stats[96 + c] / n - mean * mean;
    float inv = rsqrtf(var + BN_EPS);
    float sc = gamma[c] * inv;
    scale[c] = sc;
    shift[c] = beta[c] - mean * sc;
}

// ============================================================================
extern "C" void kernel_launch(void* const* d_in, const int* in_sizes, int n_in,
                              void* d_out, int out_size) {
    const float* x   = (const float*)d_in[0];
    const float* ew  = (const float*)d_in[1];
    const int*   row = (const int*)  d_in[2];
    const int*   col = (const int*)  d_in[3];
    const float* W1  = (const float*)d_in[4];
    // b1 = d_in[5]  -- absorbed exactly by BatchNorm mean, skipped
    const float* W2  = (const float*)d_in[6];
    // b2 = d_in[7]  -- absorbed exactly by BatchNorm mean, skipped
    const float* W3  = (const float*)d_in[8];
    const float* b3  = (const float*)d_in[9];
    const float* g1  = (const float*)d_in[10];
    const float* be1 = (const float*)d_in[11];
    const float* g2  = (const float*)d_in[12];
    const float* be2 = (const float*)d_in[13];

    int N = in_sizes[0] / 128;
    int E = in_sizes[1];
    if (N > MAX_N) N = MAX_N;
    if (E > MAX_E) E = MAX_E;
    float* out = (float*)d_out;

    float *t, *agg, *stats, *scale, *shift, *eew;
    int *deg, *starts, *cursor, *ecol;
    cudaGetSymbolAddress((void**)&t,      d_t);
    cudaGetSymbolAddress((void**)&agg,    d_agg);
    cudaGetSymbolAddress((void**)&stats,  d_stats);
    cudaGetSymbolAddress((void**)&scale,  d_scale);
    cudaGetSymbolAddress((void**)&shift,  d_shift);
    cudaGetSymbolAddress((void**)&deg,    d_deg);
    cudaGetSymbolAddress((void**)&starts, d_starts);
    cudaGetSymbolAddress((void**)&cursor, d_cursor);
    cudaGetSymbolAddress((void**)&ecol,   d_ecol);
    cudaGetSymbolAddress((void**)&eew,    d_eew);

    const int SM1 = (128*96 + 128*36) * sizeof(float);
    const int SM2 = (96*96  + 96*36)  * sizeof(float);
    const int SM3 = (96*64  + 96*36)  * sizeof(float);
    cudaFuncSetAttribute(gemm_bn_kernel<128,96>, cudaFuncAttributeMaxDynamicSharedMemorySize, SM1);
    cudaFuncSetAttribute(gemm_bn_kernel<96,96>,  cudaFuncAttributeMaxDynamicSharedMemorySize, SM2);
    cudaFuncSetAttribute(gemm_bn_kernel<96,64>,  cudaFuncAttributeMaxDynamicSharedMemorySize, SM3);

    int gblocks = (N + 31) / 32;
    int eblocks = (E + 255) / 256;
    int nwarp_blocks = (N * 32 + 255) / 256;

    // ---------------- CSR build (row-sorted edges) ----------------
    cudaMemsetAsync(deg, 0, (long)N * sizeof(int));
    hist_kernel<<<eblocks, 256>>>(row, deg, E);
    scan_kernel<<<1, 1024>>>(deg, starts, cursor, N);
    permute_kernel<<<eblocks, 256>>>(row, col, ew, cursor, ecol, eew, E);

    // ---------------- Layer 1: x[N,128] @ W1 -> gather -> agg ----------------
    cudaMemsetAsync(stats, 0, 192 * sizeof(float));
    gemm_bn_kernel<128,96><<<gblocks, dim3(24,8), SM1>>>(x, W1, nullptr, nullptr, t, N);
    gather96_kernel<<<nwarp_blocks, 256>>>(starts, ecol, eew, t, agg, N);
    stats96_kernel<<<1024, 96>>>(agg, stats, N);
    bn_finalize_kernel<<<1, 96>>>(stats, g1, be1, scale, shift, N);

    // ---------------- Layer 2: relu(bn(agg)) @ W2 -> gather -> agg -----------
    gemm_bn_kernel<96,96><<<gblocks, dim3(24,8), SM2>>>(agg, W2, scale, shift, t, N);
    cudaMemsetAsync(stats, 0, 192 * sizeof(float));
    gather96_kernel<<<nwarp_blocks, 256>>>(starts, ecol, eew, t, agg, N);
    stats96_kernel<<<1024, 96>>>(agg, stats, N);
    bn_finalize_kernel<<<1, 96>>>(stats, g2, be2, scale, shift, N);

    // ---------------- Layer 3: relu(bn(agg)) @ W3 -> gather+lsm -> out -------
    gemm_bn_kernel<96,64><<<gblocks, dim3(16,8), SM3>>>(agg, W3, scale, shift, t, N);
    gather64_lsm_kernel<<<nwarp_blocks, 256>>>(starts, ecol, eew, t, b3, out, N);
}

// round 4
// speedup vs baseline: 1.9207x; 1.1569x over previous
#include <cuda_runtime.h>
#include <cuda_bf16.h>
#include <math.h>

#define MAX_N 50000
#define MAX_E 800000
#define CH    96
#define BN_EPS 1e-5f

// -------- scratch (device globals; no allocation allowed) --------
__device__ float d_t   [MAX_N * CH];     // GEMM output (pre-aggregation)
__device__ float d_agg [MAX_N * CH];     // aggregation output
__device__ float d_stats[2 * CH];        // per-channel sum / sumsq
__device__ float d_scale[CH];
__device__ float d_shift[CH];
// CSR build scratch
__device__ int   d_deg   [MAX_N];
__device__ int   d_starts[MAX_N + 1];
__device__ int   d_cursor[MAX_N];
__device__ int2  d_epack [MAX_E];        // packed (col, bitcast(ew))

// ============================================================================
// CSR build: histogram -> scan -> permute
// ============================================================================
__global__ void hist_kernel(const int* __restrict__ row, int* __restrict__ deg, int E) {
    int i = blockIdx.x * blockDim.x + threadIdx.x;
    if (i < E) atomicAdd(&deg[row[i]], 1);
}

__global__ void scan_kernel(const int* __restrict__ deg,
                            int* __restrict__ starts,
                            int* __restrict__ cursor, int N) {
    __shared__ int part[1024];
    int t = threadIdx.x;
    int chunk = (N + 1023) / 1024;
    int lo = t * chunk;
    int hi = lo + chunk; if (hi > N) hi = N; if (lo > N) lo = N;
    int s = 0;
    for (int i = lo; i < hi; i++) s += deg[i];
    part[t] = s;
    __syncthreads();
    for (int o = 1; o < 1024; o <<= 1) {
        int v = (t >= o) ? part[t - o] : 0;
        __syncthreads();
        part[t] += v;
        __syncthreads();
    }
    int base = (t == 0) ? 0 : part[t - 1];
    for (int i = lo; i < hi; i++) {
        starts[i] = base;
        cursor[i] = base;
        base += deg[i];
    }
    if (t == 1023) starts[N] = part[1023];
}

__global__ void permute_kernel(const int* __restrict__ row,
                               const int* __restrict__ col,
                               const float* __restrict__ ew,
                               int* __restrict__ cursor,
                               int2* __restrict__ epack, int E) {
    int i = blockIdx.x * blockDim.x + threadIdx.x;
    if (i >= E) return;
    int p = atomicAdd(&cursor[row[i]], 1);
    epack[p] = make_int2(col[i], __float_as_int(ew[i]));
}

// ============================================================================
// Register-blocked GEMM with K-chunked smem staging (KC=32) and optional
// fused BatchNorm+ReLU on the INPUT. 32 rows x COUT per block; 4x4 per thread.
// ============================================================================
template<int CIN, int COUT>
__global__ void gemm_bn_kernel(const float* __restrict__ A,
                               const float* __restrict__ W,
                               const float* __restrict__ scale,
                               const float* __restrict__ shift,
                               float* __restrict__ C, int nrows) {
    constexpr int TM = 32;
    constexpr int KC = 32;            // K-chunk
    constexpr int TX = COUT / 4;
    constexpr int TY = TM / 4;
    constexpr int NT = TX * TY;
    constexpr int APAD = TM + 4;
    constexpr int KGC = KC / 4;

    __shared__ float Ws[KC * COUT];
    __shared__ float As[KC * APAD];

    int tid = threadIdx.y * TX + threadIdx.x;
    int row0 = blockIdx.x * TM;
    int c0 = threadIdx.x * 4;
    int r0 = threadIdx.y * 4;

    float acc00=0,acc01=0,acc02=0,acc03=0;
    float acc10=0,acc11=0,acc12=0,acc13=0;
    float acc20=0,acc21=0,acc22=0,acc23=0;
    float acc30=0,acc31=0,acc32=0,acc33=0;

    for (int k0 = 0; k0 < CIN; k0 += KC) {
        // stage W chunk (coalesced float4)
        for (int i = tid; i < KC * COUT / 4; i += NT)
            ((float4*)Ws)[i] = ((const float4*)(W + k0 * COUT))[i];
        // stage A chunk transposed, with optional BN+ReLU
        for (int i = tid; i < TM * KGC; i += NT) {
            int r  = i / KGC;
            int kg = i % KGC;
            int grow = row0 + r;
            float4 v = make_float4(0.f, 0.f, 0.f, 0.f);
            if (grow < nrows)
                v = *(const float4*)(A + (long)grow * CIN + k0 + kg * 4);
            if (scale) {
                int k = k0 + kg * 4;
                v.x = fmaxf(fmaf(v.x, scale[k+0], shift[k+0]), 0.f);
                v.y = fmaxf(fmaf(v.y, scale[k+1], shift[k+1]), 0.f);
                v.z = fmaxf(fmaf(v.z, scale[k+2], shift[k+2]), 0.f);
                v.w = fmaxf(fmaf(v.w, scale[k+3], shift[k+3]), 0.f);
            }
            As[(kg*4+0) * APAD + r] = v.x;
            As[(kg*4+1) * APAD + r] = v.y;
            As[(kg*4+2) * APAD + r] = v.z;
            As[(kg*4+3) * APAD + r] = v.w;
        }
        __syncthreads();

#pragma unroll 8
        for (int kk = 0; kk < KC; kk++) {
            float4 w = *(const float4*)(Ws + kk * COUT + c0);
            const float* ar = As + kk * APAD + r0;
            float a0 = ar[0], a1 = ar[1], a2 = ar[2], a3 = ar[3];
            acc00 = fmaf(a0, w.x, acc00); acc01 = fmaf(a0, w.y, acc01);
            acc02 = fmaf(a0, w.z, acc02); acc03 = fmaf(a0, w.w, acc03);
            acc10 = fmaf(a1, w.x, acc10); acc11 = fmaf(a1, w.y, acc11);
            acc12 = fmaf(a1, w.z, acc12); acc13 = fmaf(a1, w.w, acc13);
            acc20 = fmaf(a2, w.x, acc20); acc21 = fmaf(a2, w.y, acc21);
            acc22 = fmaf(a2, w.z, acc22); acc23 = fmaf(a2, w.w, acc23);
            acc30 = fmaf(a3, w.x, acc30); acc31 = fmaf(a3, w.y, acc31);
            acc32 = fmaf(a3, w.z, acc32); acc33 = fmaf(a3, w.w, acc33);
        }
        __syncthreads();
    }

    long base = (long)(row0 + r0) * COUT + c0;
    if (row0 + r0 + 0 < nrows) *(float4*)(C + base + 0L*COUT) = make_float4(acc00,acc01,acc02,acc03);
    if (row0 + r0 + 1 < nrows) *(float4*)(C + base + 1L*COUT) = make_float4(acc10,acc11,acc12,acc13);
    if (row0 + r0 + 2 < nrows) *(float4*)(C + base + 2L*COUT) = make_float4(acc20,acc21,acc22,acc23);
    if (row0 + r0 + 3 < nrows) *(float4*)(C + base + 3L*COUT) = make_float4(acc30,acc31,acc32,acc33);
}

// ============================================================================
// CSR gather (96 ch, no atomics): one warp per node, lanes 0-23 each own a
// float4 channel group -> ONE LDG.128 per edge. Pack prefetch pipelining.
// ============================================================================
__global__ void gather96_kernel(const int* __restrict__ starts,
                                const int2* __restrict__ epack,
                                const float* __restrict__ src,
                                float* __restrict__ dst, int N) {
    int w = (blockIdx.x * blockDim.x + threadIdx.x) >> 5;
    int lane = threadIdx.x & 31;
    if (w >= N) return;
    int s = __ldg(starts + w), e = __ldg(starts + w + 1);
    bool act = lane < 24;
    float4 acc = make_float4(0.f, 0.f, 0.f, 0.f);
    int2 pk = make_int2(0, 0);
    if (s < e) pk = __ldg(epack + s);
    for (int i = s; i < e; i++) {
        int c = pk.x; float cw = __int_as_float(pk.y);
        if (i + 1 < e) pk = __ldg(epack + i + 1);
        float4 v = make_float4(0.f, 0.f, 0.f, 0.f);
        if (act) v = __ldg(((const float4*)(src + (long)c * 96)) + lane);
        acc.x = fmaf(cw, v.x, acc.x);
        acc.y = fmaf(cw, v.y, acc.y);
        acc.z = fmaf(cw, v.z, acc.z);
        acc.w = fmaf(cw, v.w, acc.w);
    }
    if (act) ((float4*)(dst + (long)w * 96))[lane] = acc;
}

// ============================================================================
// CSR gather (64 ch) with 2 edges/iter (half-warps), fused +bias + log_softmax.
// ============================================================================
__global__ void gather64_lsm_kernel(const int* __restrict__ starts,
                                    const int2* __restrict__ epack,
                                    const float* __restrict__ src,
                                    const float* __restrict__ b,
                                    float* __restrict__ out, int N) {
    int w = (blockIdx.x * blockDim.x + threadIdx.x) >> 5;
    int lane = threadIdx.x & 31;
    if (w >= N) return;
    int half = lane >> 4;       // 0 or 1: which edge of the pair
    int q = lane & 15;          // float4 channel group
    int s = __ldg(starts + w), e = __ldg(starts + w + 1);
    float4 acc = make_float4(0.f, 0.f, 0.f, 0.f);
    int i0 = s + half;
    int2 pk = make_int2(0, 0);
    if (i0 < e) pk = __ldg(epack + i0);
    for (int i = i0; i < e; i += 2) {
        int c = pk.x; float cw = __int_as_float(pk.y);
        if (i + 2 < e) pk = __ldg(epack + i + 2);
        float4 v = __ldg(((const float4*)(src + (long)c * 64)) + q);
        acc.x = fmaf(cw, v.x, acc.x);
        acc.y = fmaf(cw, v.y, acc.y);
        acc.z = fmaf(cw, v.z, acc.z);
        acc.w = fmaf(cw, v.w, acc.w);
    }
    // combine the two half-warp edge subsets
    acc.x += __shfl_xor_sync(0xFFFFFFFFu, acc.x, 16);
    acc.y += __shfl_xor_sync(0xFFFFFFFFu, acc.y, 16);
    acc.z += __shfl_xor_sync(0xFFFFFFFFu, acc.z, 16);
    acc.w += __shfl_xor_sync(0xFFFFFFFFu, acc.w, 16);
    float4 bb = __ldg(((const float4*)b) + q);
    float v0 = acc.x + bb.x, v1 = acc.y + bb.y, v2 = acc.z + bb.z, v3 = acc.w + bb.w;
    float m = fmaxf(fmaxf(v0, v1), fmaxf(v2, v3));
#pragma unroll
    for (int o = 8; o; o >>= 1) m = fmaxf(m, __shfl_xor_sync(0xFFFFFFFFu, m, o));
    float sm = __expf(v0 - m) + __expf(v1 - m) + __expf(v2 - m) + __expf(v3 - m);
#pragma unroll
    for (int o = 8; o; o >>= 1) sm += __shfl_xor_sync(0xFFFFFFFFu, sm, o);
    float l = m + __logf(sm);
    if (half == 0)
        ((float4*)(out + (long)w * 64))[q] = make_float4(v0 - l, v1 - l, v2 - l, v3 - l);
}

// -------- BN stats: register-accumulating, one thread per channel ----------
__global__ void stats96_kernel(const float* __restrict__ h,
                               float* __restrict__ stats, int nrows) {
    int c = threadIdx.x;   // blockDim.x == 96
    float s = 0.f, q = 0.f;
    for (int r = blockIdx.x; r < nrows; r += gridDim.x) {
        float v = h[(long)r * 96 + c];
        s += v;
        q = fmaf(v, v, q);
    }
    atomicAdd(&stats[c], s);
    atomicAdd(&stats[96 + c], q);
}

// -------- BN finalize: per-channel scale/shift --------
__global__ void bn_finalize_kernel(const float* __restrict__ stats,
                                   const float* __restrict__ gamma,
                                   const float* __restrict__ beta,
                                   float* __restrict__ scale,
                                   float* __restrict__ shift, int nrows) {
    int c = threadIdx.x;
    if (c >= 96) return;
    float n = (float)nrows;
    float mean = stats[c] / n;
    float var = stats[96 + c] / n - mean * mean;
    float inv = rsqrtf(var + BN_EPS);
    float sc = gamma[c] * inv;
    scale[c] = sc;
    shift[c] = beta[c] - mean * sc;
}

// ============================================================================
extern "C" void kernel_launch(void* const* d_in, const int* in_sizes, int n_in,
                              void* d_out, int out_size) {
    const float* x   = (const float*)d_in[0];
    const float* ew  = (const float*)d_in[1];
    const int*   row = (const int*)  d_in[2];
    const int*   col = (const int*)  d_in[3];
    const float* W1  = (const float*)d_in[4];
    // b1 = d_in[5]  -- absorbed exactly by BatchNorm mean, skipped
    const float* W2  = (const float*)d_in[6];
    // b2 = d_in[7]  -- absorbed exactly by BatchNorm mean, skipped
    const float* W3  = (const float*)d_in[8];
    const float* b3  = (const float*)d_in[9];
    const float* g1  = (const float*)d_in[10];
    const float* be1 = (const float*)d_in[11];
    const float* g2  = (const float*)d_in[12];
    const float* be2 = (const float*)d_in[13];

    int N = in_sizes[0] / 128;
    int E = in_sizes[1];
    if (N > MAX_N) N = MAX_N;
    if (E > MAX_E) E = MAX_E;
    float* out = (float*)d_out;

    float *t, *agg, *stats, *scale, *shift;
    int *deg, *starts, *cursor;
    int2 *epack;
    cudaGetSymbolAddress((void**)&t,      d_t);
    cudaGetSymbolAddress((void**)&agg,    d_agg);
    cudaGetSymbolAddress((void**)&stats,  d_stats);
    cudaGetSymbolAddress((void**)&scale,  d_scale);
    cudaGetSymbolAddress((void**)&shift,  d_shift);
    cudaGetSymbolAddress((void**)&deg,    d_deg);
    cudaGetSymbolAddress((void**)&starts, d_starts);
    cudaGetSymbolAddress((void**)&cursor, d_cursor);
    cudaGetSymbolAddress((void**)&epack,  d_epack);

    int gblocks = (N + 31) / 32;
    int eblocks = (E + 255) / 256;
    int nwarp_blocks = (N * 32 + 255) / 256;

    // ---------------- CSR build (row-sorted packed edges) ----------------
    cudaMemsetAsync(deg, 0, (long)N * sizeof(int));
    hist_kernel<<<eblocks, 256>>>(row, deg, E);
    scan_kernel<<<1, 1024>>>(deg, starts, cursor, N);
    permute_kernel<<<eblocks, 256>>>(row, col, ew, cursor, epack, E);

    // ---------------- Layer 1: x[N,128] @ W1 -> gather -> agg ----------------
    cudaMemsetAsync(stats, 0, 192 * sizeof(float));
    gemm_bn_kernel<128,96><<<gblocks, dim3(24,8)>>>(x, W1, nullptr, nullptr, t, N);
    gather96_kernel<<<nwarp_blocks, 256>>>(starts, epack, t, agg, N);
    stats96_kernel<<<1024, 96>>>(agg, stats, N);
    bn_finalize_kernel<<<1, 96>>>(stats, g1, be1, scale, shift, N);

    // ---------------- Layer 2: relu(bn(agg)) @ W2 -> gather -> agg -----------
    gemm_bn_kernel<96,96><<<gblocks, dim3(24,8)>>>(agg, W2, scale, shift, t, N);
    cudaMemsetAsync(stats, 0, 192 * sizeof(float));
    gather96_kernel<<<nwarp_blocks, 256>>>(starts, epack, t, agg, N);
    stats96_kernel<<<1024, 96>>>(agg, stats, N);
    bn_finalize_kernel<<<1, 96>>>(stats, g2, be2, scale, shift, N);

    // ---------------- Layer 3: relu(bn(agg)) @ W3 -> gather+lsm -> out -------
    gemm_bn_kernel<96,64><<<gblocks, dim3(16,8)>>>(agg, W3, scale, shift, t, N);
    gather64_lsm_kernel<<<nwarp_blocks, 256>>>(starts, epack, t, b3, out, N);
}